// round 11
// baseline (speedup 1.0000x reference)
#include <cuda_runtime.h>
#include <cuda_bf16.h>
#include <math.h>
#include <stdint.h>

// ---------------- problem constants ----------------
#define BBATCH 2
#define LSEQ   96
#define CDIM   512
#define C3     1536
#define CH     2048
#define NHEADS 16
#define HDIM   32
#define SPA    (LSEQ*LSEQ)          // 9216
#define NTOK   (BBATCH*SPA)         // 18432
#define BC     (BBATCH*CDIM)        // 1024

// ---------------- scratch (device globals) ----------------
__device__ float          g_sum[BC];
__device__ float          g_sq[BC];
__device__ float          g_lut[BC];
__device__ __nv_bfloat16  g_xn[NTOK*CDIM];
__device__ __nv_bfloat16  g_win[C3*CDIM];
__device__ __nv_bfloat16  g_wout[CDIM*CDIM];
__device__ __nv_bfloat16  g_wfc1[CH*CDIM];
__device__ __nv_bfloat16  g_wfc2[CDIM*CH];
__device__ __nv_bfloat16  g_Qb[(size_t)NTOK*CDIM];   // [b*16+h][ij][d]
__device__ __nv_bfloat16  g_Kb[(size_t)NTOK*CDIM];
__device__ __nv_bfloat16  g_Vb[(size_t)NTOK*CDIM];
__device__ float          g_bias[2*NHEADS*SPA];
__device__ __nv_bfloat16  g_attA[(size_t)NTOK*CDIM];
__device__ __nv_bfloat16  g_attB[(size_t)NTOK*CDIM];
__device__ __nv_bfloat16  g_abf[NTOK*CDIM];
__device__ float          g_x1[(size_t)NTOK*CDIM];
__device__ __nv_bfloat16  g_x1bf[NTOK*CDIM];
__device__ __nv_bfloat16  g_h[(size_t)NTOK*CH];
__device__ __nv_bfloat16  g_mb[(size_t)NTOK*CDIM];

// ---------------- helpers ----------------
__device__ __forceinline__ float wsum(float v){
    #pragma unroll
    for (int o = 16; o; o >>= 1) v += __shfl_xor_sync(0xffffffffu, v, o);
    return v;
}
__device__ __forceinline__ int pymod(int a, int m){
    int r = a % m; if (r && ((r < 0) != (m < 0))) r += m; return r;
}
__device__ __forceinline__ void ld4(const float* p, float v[4]){
    float4 t = *(const float4*)p; v[0]=t.x; v[1]=t.y; v[2]=t.z; v[3]=t.w;
}
__device__ __forceinline__ void ld4(const __nv_bfloat16* p, float v[4]){
    uint2 t = *(const uint2*)p;
    __nv_bfloat162 a = *(__nv_bfloat162*)&t.x;
    __nv_bfloat162 b = *(__nv_bfloat162*)&t.y;
    v[0]=__bfloat162float(a.x); v[1]=__bfloat162float(a.y);
    v[2]=__bfloat162float(b.x); v[3]=__bfloat162float(b.y);
}
__device__ __forceinline__ uint2 pack4(float a, float b, float c, float d){
    __nv_bfloat162 lo = __floats2bfloat162_rn(a, b);
    __nv_bfloat162 hi = __floats2bfloat162_rn(c, d);
    uint2 r; r.x = *(uint32_t*)&lo; r.y = *(uint32_t*)&hi; return r;
}
__device__ __forceinline__ uint32_t smem_u32(const void* p){
    return (uint32_t)__cvta_generic_to_shared(p);
}
__device__ __forceinline__ void cpasync16(void* s, const void* g){
    asm volatile("cp.async.cg.shared.global [%0], [%1], 16;\n"
        :: "r"(smem_u32(s)), "l"(g));
}
__device__ __forceinline__ void cp_commit(){ asm volatile("cp.async.commit_group;\n" ::); }
__device__ __forceinline__ void ldsm_x4(uint32_t &r0, uint32_t &r1, uint32_t &r2, uint32_t &r3,
                                        uint32_t addr){
    asm volatile("ldmatrix.sync.aligned.m8n8.x4.shared.b16 {%0,%1,%2,%3}, [%4];"
        : "=r"(r0), "=r"(r1), "=r"(r2), "=r"(r3) : "r"(addr));
}
__device__ __forceinline__ void mma16816(float c[4],
        uint32_t a0, uint32_t a1, uint32_t a2, uint32_t a3,
        uint32_t b0, uint32_t b1){
    asm volatile(
        "mma.sync.aligned.m16n8k16.row.col.f32.bf16.bf16.f32 "
        "{%0,%1,%2,%3}, {%4,%5,%6,%7}, {%8,%9}, {%0,%1,%2,%3};\n"
        : "+f"(c[0]), "+f"(c[1]), "+f"(c[2]), "+f"(c[3])
        : "r"(a0), "r"(a1), "r"(a2), "r"(a3), "r"(b0), "r"(b1));
}
// gelu via tanh approximation
__device__ __forceinline__ float gelu_t(float v){
    float y = 0.7978845608028654f*(v + 0.044715f*v*v*v);
    float e = __expf(2.0f*y);
    float t = 1.0f - 2.0f/(e + 1.0f);
    return 0.5f*v*(1.0f + t);
}

// ---------------- per-(b,c) sum/sumsq over spatial ----------------
template<typename T>
__global__ void k_stats(const T* __restrict__ in, const T* __restrict__ in2){
    const int b  = blockIdx.y;
    const int s0 = blockIdx.x * 32;
    const int c4 = threadIdx.x * 4;
    float s[4] = {0,0,0,0}, q[4] = {0,0,0,0};
    for (int ss = 0; ss < 32; ss++){
        size_t off = ((size_t)b*SPA + s0 + ss)*CDIM + c4;
        float v[4]; ld4(in + off, v);
        if (in2){
            float w[4]; ld4(in2 + off, w);
            #pragma unroll
            for (int j=0;j<4;j++) v[j] = 0.5f*(v[j] + w[j]);
        }
        #pragma unroll
        for (int j=0;j<4;j++){ s[j] += v[j]; q[j] += v[j]*v[j]; }
    }
    #pragma unroll
    for (int j=0;j<4;j++){
        atomicAdd(&g_sum[b*CDIM + c4 + j], s[j]);
        atomicAdd(&g_sq [b*CDIM + c4 + j], q[j]);
    }
}

// ---------------- scale LUT: w*gamma/(std+eps); then reset stats ----------------
__global__ void k_scale(const float* __restrict__ w, const float* __restrict__ gamma,
                        float eps){
    int i = blockIdx.x*256 + threadIdx.x;
    if (i < BC){
        int c = i & (CDIM-1);
        float s = g_sum[i], q = g_sq[i];
        float var = (q - s*s*(1.0f/(float)SPA)) * (1.0f/(float)(SPA-1));
        float stdv = sqrtf(fmaxf(var, 0.f));
        float g = gamma ? gamma[c] : 1.0f;
        g_lut[i] = w[c]*g/(stdv + eps);
        g_sum[i] = 0.f;
        g_sq[i]  = 0.f;
    }
}

// rms-inorm apply via LUT -> bf16; optional 0.5*(A+B); optional weight conversion
template<typename T>
__global__ void k_apply(const T* __restrict__ in, const T* __restrict__ in2,
                        __nv_bfloat16* __restrict__ outb,
                        const float* __restrict__ cw0, __nv_bfloat16* __restrict__ cd0,
                        const float* __restrict__ cw1, __nv_bfloat16* __restrict__ cd1,
                        const float* __restrict__ cw2, __nv_bfloat16* __restrict__ cd2,
                        const float* __restrict__ cw3, __nv_bfloat16* __restrict__ cd3){
    size_t i4  = (size_t)blockIdx.x*256 + threadIdx.x;
    size_t ele = i4*4;
    int c = (int)(ele & (CDIM-1));
    int b = (int)(ele / ((size_t)SPA*CDIM));
    float v[4]; ld4(in + ele, v);
    if (in2){
        float u[4]; ld4(in2 + ele, u);
        #pragma unroll
        for (int j=0;j<4;j++) v[j] = 0.5f*(v[j] + u[j]);
    }
    float4 sc = *(const float4*)(g_lut + b*CDIM + c);
    ((uint2*)outb)[i4] = pack4(v[0]*sc.x, v[1]*sc.y, v[2]*sc.z, v[3]*sc.w);

    if (cw0){
        int blk = blockIdx.x;
        const float* src = nullptr; __nv_bfloat16* dst = nullptr; int off = 0;
        if      (blk < 768)  { src = cw0; dst = cd0; off = blk; }
        else if (blk < 1024) { src = cw1; dst = cd1; off = blk - 768; }
        else if (blk < 2048) { src = cw2; dst = cd2; off = blk - 1024; }
        else if (blk < 3072) { src = cw3; dst = cd3; off = blk - 2048; }
        if (src){
            int wi = off*256 + threadIdx.x;
            float4 t = ((const float4*)src)[wi];
            ((uint2*)dst)[wi] = pack4(t.x, t.y, t.z, t.w);
        }
    }
}

// final: out = x1 + m*lut
__global__ void k_final(float* __restrict__ out){
    size_t i4  = (size_t)blockIdx.x*256 + threadIdx.x;
    size_t ele = i4*4;
    int c = (int)(ele & (CDIM-1));
    int b = (int)(ele / ((size_t)SPA*CDIM));
    float m[4]; ld4(g_mb + ele, m);
    float4 x1 = *(const float4*)(g_x1 + ele);
    float4 sc = *(const float4*)(g_lut + b*CDIM + c);
    float4 r;
    r.x = x1.x + m[0]*sc.x;
    r.y = x1.y + m[1]*sc.y;
    r.z = x1.z + m[2]*sc.z;
    r.w = x1.w + m[3]*sc.w;
    *(float4*)(out + ele) = r;
}

// ---------------- bf16 mma GEMM: 128x64 tile, 4-stage cp.async, 3 CTAs/SM ------
// C[M,N] = A[M,K] * B[N,K]^T
#define GBM 128
#define GBN 64
#define GBK 32
#define GSTR 40
#define GSLOT ((GBM+GBN)*GSTR)          // 7680 elems per stage
#define GEMM_SMEM (4*GSLOT*2)           // 61440 bytes
#define TSTR 68                         // f32 epilogue tile stride (MODE 4)

// MODE 1: y=(acc+bias)*gamma+res -> Cf f32 + Cb bf16
// MODE 2: Cb = bf16(gelu(acc+bias))
// MODE 3: Cb = bf16(acc+bias)
// MODE 4: qkv epilogue: per-segment q/k LayerNorm + transpose into g_Qb/g_Kb/g_Vb
template<int MODE>
__global__ void __launch_bounds__(256,3) k_gemm(
        const __nv_bfloat16* __restrict__ A, const __nv_bfloat16* __restrict__ Bw,
        const float* __restrict__ bias, const float* __restrict__ gamma,
        const float* __restrict__ res,
        float* __restrict__ Cf, __nv_bfloat16* __restrict__ Cb,
        const float* __restrict__ qw, const float* __restrict__ qb,
        const float* __restrict__ kw, const float* __restrict__ kb,
        int Nn, int K){
    extern __shared__ __nv_bfloat16 smg[];
    const int tid  = threadIdx.x;
    const int lane = tid & 31, warp = tid >> 5;
    const int gid  = lane >> 2, tig = lane & 3;
    const int wm   = warp >> 2, wn  = warp & 3;    // 2 x 4 warps, 64x16 warp tile
    const int bm   = blockIdx.y * GBM;
    const int bn   = blockIdx.x * GBN;

    const int aRow    = wm*64 + ((lane>>3)&1)*8 + (lane&7);
    const int aColOff = (lane>>4)*8;
    const int bRow    = wn*16 + ((lane>>4)&1)*8 + (lane&7);
    const int bColOff = ((lane>>3)&1)*8;

    float acc[4][2][4];
    #pragma unroll
    for (int mi=0; mi<4; mi++)
        #pragma unroll
        for (int ni=0; ni<2; ni++)
            #pragma unroll
            for (int r=0; r<4; r++) acc[mi][ni][r] = 0.f;

    auto load_stage = [&](int s, int k0){
        __nv_bfloat16* dA = smg + s*GSLOT;
        __nv_bfloat16* dB = dA + GBM*GSTR;
        #pragma unroll
        for (int r = 0; r < 3; r++){
            int idx = tid + r*256;          // 0..767
            int row = idx >> 2;             // 0..191
            int cv  = (idx & 3) << 3;
            if (row < GBM)
                cpasync16(dA + row*GSTR + cv, A  + (size_t)(bm+row)*K + k0 + cv);
            else
                cpasync16(dB + (row-GBM)*GSTR + cv, Bw + (size_t)(bn+row-GBM)*K + k0 + cv);
        }
    };

    const int T = K >> 5;
    load_stage(0, 0);  cp_commit();
    load_stage(1, 32); cp_commit();

    for (int it = 0; it < T; it++){
        if (it + 2 < T) load_stage((it+2)&3, (it+2) << 5);
        cp_commit();
        asm volatile("cp.async.wait_group 2;" ::: "memory");
        __syncthreads();
        const __nv_bfloat16* sA = smg + (it&3)*GSLOT;
        const __nv_bfloat16* sB = sA + GBM*GSTR;
        #pragma unroll
        for (int kk = 0; kk < GBK; kk += 16){
            uint32_t af[4][4], bfr[2][2];
            #pragma unroll
            for (int mi=0; mi<4; mi++){
                uint32_t addr = smem_u32(sA + (aRow + mi*16)*GSTR + kk + aColOff);
                ldsm_x4(af[mi][0], af[mi][1], af[mi][2], af[mi][3], addr);
            }
            {
                uint32_t addr = smem_u32(sB + bRow*GSTR + kk + bColOff);
                ldsm_x4(bfr[0][0], bfr[0][1], bfr[1][0], bfr[1][1], addr);
            }
            #pragma unroll
            for (int mi=0; mi<4; mi++)
                #pragma unroll
                for (int ni=0; ni<2; ni++)
                    mma16816(acc[mi][ni], af[mi][0], af[mi][1], af[mi][2], af[mi][3],
                             bfr[ni][0], bfr[ni][1]);
        }
    }

    if (MODE == 4){
        // ---- fused q/k LayerNorm + head transpose epilogue ----
        float* sT = (float*)smg;                                     // 128 x TSTR f32
        __nv_bfloat16* sStage = (__nv_bfloat16*)((char*)smg + 128*TSTR*4);
        __syncthreads();
        #pragma unroll
        for (int mi=0; mi<4; mi++){
            int r0 = wm*64 + mi*16 + gid;
            #pragma unroll
            for (int ni=0; ni<2; ni++){
                int c = wn*16 + ni*8 + tig*2;
                float b0 = bias[bn + c], b1 = bias[bn + c + 1];
                *(float2*)(sT + r0*TSTR + c)     = make_float2(acc[mi][ni][0]+b0, acc[mi][ni][1]+b1);
                *(float2*)(sT + (r0+8)*TSTR + c) = make_float2(acc[mi][ni][2]+b0, acc[mi][ni][3]+b1);
            }
        }
        __syncthreads();
        const int b   = bm / SPA;
        const int ij0 = bm % SPA;
        #pragma unroll
        for (int seg = 0; seg < 2; seg++){
            int segidx = (bn >> 5) + seg;
            int t = segidx % 3, h = segidx / 3;
            const float* lw = (t == 0) ? qw : kw;
            const float* lb = (t == 0) ? qb : kb;
            float wv = (t < 2) ? lw[lane] : 0.f;
            float bv = (t < 2) ? lb[lane] : 0.f;
            for (int rr = 0; rr < 16; rr++){
                int row = warp*16 + rr;
                float val = sT[row*TSTR + seg*32 + lane];
                if (t < 2){
                    float mu = wsum(val) * (1.f/32.f);
                    float d  = val - mu;
                    float vr = wsum(d*d) * (1.f/32.f);
                    val = d * rsqrtf(vr + 1e-5f) * wv + bv;
                }
                sStage[row*32 + lane] = __float2bfloat16(val);
            }
            __syncthreads();
            __nv_bfloat16* dst = ((t == 0) ? g_Qb : (t == 1) ? g_Kb : g_Vb)
                                 + ((size_t)(b*NHEADS + h)*SPA + ij0)*HDIM;
            #pragma unroll
            for (int i = tid; i < 512; i += 256)
                ((uint4*)dst)[i] = ((const uint4*)sStage)[i];
            __syncthreads();
        }
        return;
    }

    // standard epilogues
    #pragma unroll
    for (int mi=0; mi<4; mi++){
        int r0 = bm + wm*64 + mi*16 + gid;
        #pragma unroll
        for (int ni=0; ni<2; ni++){
            int c = bn + wn*16 + ni*8 + tig*2;
            #pragma unroll
            for (int half=0; half<2; half++){
                int r = r0 + half*8;
                float v0 = acc[mi][ni][half*2+0] + bias[c];
                float v1 = acc[mi][ni][half*2+1] + bias[c+1];
                size_t o = (size_t)r*Nn + c;
                if (MODE == 1){
                    float y0 = v0*gamma[c]   + res[o];
                    float y1 = v1*gamma[c+1] + res[o+1];
                    *(float2*)(Cf + o) = make_float2(y0, y1);
                    *(__nv_bfloat162*)(Cb + o) = __floats2bfloat162_rn(y0, y1);
                } else if (MODE == 2){
                    *(__nv_bfloat162*)(Cb + o) = __floats2bfloat162_rn(gelu_t(v0), gelu_t(v1));
                } else {
                    *(__nv_bfloat162*)(Cb + o) = __floats2bfloat162_rn(v0, v1);
                }
            }
        }
    }
}

// ---------------- T5 relative position bias ----------------
__global__ void k_bias(const float* __restrict__ emb, const int* __restrict__ bcs){
    int idx = blockIdx.x*256 + threadIdx.x;
    int dir = idx / SPA;
    int qk  = idx % SPA;
    int q = qk / LSEQ, kk = qk % LSEQ;
    int bc = bcs[dir];
    int rel = kk - q;
    if (bc == 1){
        const int thr = LSEQ/2;
        if      (rel < -thr) rel = pymod(rel,  thr);
        else if (rel >  thr) rel = pymod(rel, -thr);
    }
    int n = -rel;
    int ret = (n < 0) ? 16 : 0;
    n = (n < 0) ? -n : n;
    int bucket;
    if (n < 8) bucket = ret + n;
    else {
        int vl = 8 + (int)(logf((float)n * 0.125f) / logf(4.0f) * 8.0f);
        if (vl > 15) vl = 15;
        bucket = ret + vl;
    }
    #pragma unroll
    for (int h = 0; h < NHEADS; h++)
        g_bias[(dir*NHEADS + h)*SPA + qk] = emb[bucket*NHEADS + h];
}

// ---------------- tensor-core axial attention (mma.sync) ----------------
#define AQSTR 40
#define AVSTR 106
#define ASSTR 100
#define APSTR 104
#define OFF_K  (96*AQSTR)
#define OFF_VT (2*96*AQSTR)
#define OFF_S_BYTES  ((2*96*AQSTR + 32*AVSTR)*2)
#define OFF_P_BYTES  (OFF_S_BYTES + 96*ASSTR*4)
#define ATT_SMEM (OFF_P_BYTES + 96*APSTR*2)

__global__ void __launch_bounds__(256,2) k_attn(){
    extern __shared__ char smraw[];
    __nv_bfloat16* sQ  = (__nv_bfloat16*)smraw;
    __nv_bfloat16* sK  = sQ + OFF_K;
    __nv_bfloat16* sVt = sQ + OFF_VT;
    float*         sS  = (float*)(smraw + OFF_S_BYTES);
    __nv_bfloat16* sP  = (__nv_bfloat16*)(smraw + OFF_P_BYTES);

    const int line = blockIdx.x;
    const int bh   = blockIdx.y;
    const int dir  = blockIdx.z;
    const int head = bh & (NHEADS-1);
    const int bidx = bh >> 4;
    const int tid  = threadIdx.x;
    const int lane = tid & 31, warp = tid >> 5;
    const int gid  = lane >> 2, tig = lane & 3;
    const int wm   = warp >> 2, wn  = warp & 3;
    const size_t base = (size_t)bh * SPA * HDIM;

    for (int u = tid; u < 1536; u += 256){
        int row = u >> 4;
        int dp  = (u & 15) << 1;
        size_t g = base + dp + (size_t)HDIM * (dir == 0 ? (line*LSEQ + row)
                                                        : (row*LSEQ + line));
        *(uint32_t*)(sQ + row*AQSTR + dp) = *(const uint32_t*)(g_Qb + g);
        *(uint32_t*)(sK + row*AQSTR + dp) = *(const uint32_t*)(g_Kb + g);
        uint32_t vv = *(const uint32_t*)(g_Vb + g);
        __nv_bfloat162 v2 = *(__nv_bfloat162*)&vv;
        sVt[dp*AVSTR + row]     = v2.x;
        sVt[(dp+1)*AVSTR + row] = v2.y;
    }
    __syncthreads();

    {
        float acc[3][3][4];
        #pragma unroll
        for (int mi=0;mi<3;mi++)
            #pragma unroll
            for (int ni=0;ni<3;ni++)
                #pragma unroll
                for (int e=0;e<4;e++) acc[mi][ni][e] = 0.f;
        #pragma unroll
        for (int ks=0; ks<2; ks++){
            int kk = ks*16;
            uint32_t af[3][4], bfr[3][2];
            #pragma unroll
            for (int mi=0;mi<3;mi++){
                const __nv_bfloat16* p = sQ + (wm*48 + mi*16 + gid)*AQSTR + kk + tig*2;
                af[mi][0] = *(const uint32_t*)p;
                af[mi][1] = *(const uint32_t*)(p + 8*AQSTR);
                af[mi][2] = *(const uint32_t*)(p + 8);
                af[mi][3] = *(const uint32_t*)(p + 8*AQSTR + 8);
            }
            #pragma unroll
            for (int ni=0;ni<3;ni++){
                const __nv_bfloat16* p = sK + (wn*24 + ni*8 + gid)*AQSTR + kk + tig*2;
                bfr[ni][0] = *(const uint32_t*)p;
                bfr[ni][1] = *(const uint32_t*)(p + 8);
            }
            #pragma unroll
            for (int mi=0;mi<3;mi++)
                #pragma unroll
                for (int ni=0;ni<3;ni++)
                    mma16816(acc[mi][ni], af[mi][0], af[mi][1], af[mi][2], af[mi][3],
                             bfr[ni][0], bfr[ni][1]);
        }
        const float* bb = g_bias + (size_t)(dir*NHEADS + head)*SPA;
        const float SC = 0.17677669529663687f;
        #pragma unroll
        for (int mi=0;mi<3;mi++){
            int r = wm*48 + mi*16 + gid;
            #pragma unroll
            for (int ni=0;ni<3;ni++){
                int c = wn*24 + ni*8 + tig*2;
                sS[r*ASSTR + c]       = acc[mi][ni][0]*SC + bb[r*LSEQ + c];
                sS[r*ASSTR + c+1]     = acc[mi][ni][1]*SC + bb[r*LSEQ + c+1];
                sS[(r+8)*ASSTR + c]   = acc[mi][ni][2]*SC + bb[(r+8)*LSEQ + c];
                sS[(r+8)*ASSTR + c+1] = acc[mi][ni][3]*SC + bb[(r+8)*LSEQ + c+1];
            }
        }
    }
    __syncthreads();

    for (int r = warp; r < LSEQ; r += 8){
        const float* row = sS + r*ASSTR;
        float v0 = row[lane], v1 = row[lane+32], v2 = row[lane+64];
        float m = fmaxf(v0, fmaxf(v1, v2));
        #pragma unroll
        for (int o = 16; o; o >>= 1) m = fmaxf(m, __shfl_xor_sync(0xffffffffu, m, o));
        float e0 = __expf(v0 - m), e1 = __expf(v1 - m), e2 = __expf(v2 - m);
        float s = e0 + e1 + e2;
        #pragma unroll
        for (int o = 16; o; o >>= 1) s += __shfl_xor_sync(0xffffffffu, s, o);
        float inv = 1.0f / s;
        __nv_bfloat16* pr = sP + r*APSTR;
        pr[lane]    = __float2bfloat16(e0*inv);
        pr[lane+32] = __float2bfloat16(e1*inv);
        pr[lane+64] = __float2bfloat16(e2*inv);
    }
    __syncthreads();

    {
        float po[3][4];
        #pragma unroll
        for (int mi=0;mi<3;mi++)
            #pragma unroll
            for (int e=0;e<4;e++) po[mi][e] = 0.f;
        #pragma unroll
        for (int ks=0; ks<6; ks++){
            int kk = ks*16;
            uint32_t b0 = *(const uint32_t*)(sVt + (wn*8 + gid)*AVSTR + kk + tig*2);
            uint32_t b1 = *(const uint32_t*)(sVt + (wn*8 + gid)*AVSTR + kk + 8 + tig*2);
            #pragma unroll
            for (int mi=0;mi<3;mi++){
                const __nv_bfloat16* p = sP + (wm*48 + mi*16 + gid)*APSTR + kk + tig*2;
                uint32_t a0 = *(const uint32_t*)p;
                uint32_t a1 = *(const uint32_t*)(p + 8*APSTR);
                uint32_t a2 = *(const uint32_t*)(p + 8);
                uint32_t a3 = *(const uint32_t*)(p + 8*APSTR + 8);
                mma16816(po[mi], a0, a1, a2, a3, b0, b1);
            }
        }
        __nv_bfloat16* outp = dir ? g_attB : g_attA;
        int d = wn*8 + tig*2;
        #pragma unroll
        for (int mi=0;mi<3;mi++){
            int r = wm*48 + mi*16 + gid;
            #pragma unroll
            for (int half=0; half<2; half++){
                int q = r + half*8;
                int token = (dir == 0) ? ((bidx*LSEQ + line)*LSEQ + q)
                                       : ((bidx*LSEQ + q)*LSEQ + line);
                __nv_bfloat162 t = __floats2bfloat162_rn(po[mi][half*2], po[mi][half*2+1]);
                *(__nv_bfloat162*)(outp + (size_t)token*CDIM + head*HDIM + d) = t;
            }
        }
    }
}

// ---------------- launch ----------------
extern "C" void kernel_launch(void* const* d_in, const int* in_sizes, int n_in,
                              void* d_out, int out_size){
    const float* x        = (const float*)d_in[0];
    const float* norm1_w  = (const float*)d_in[1];
    const float* in_w     = (const float*)d_in[2];
    const float* in_b     = (const float*)d_in[3];
    const float* qn_w     = (const float*)d_in[4];
    const float* qn_b     = (const float*)d_in[5];
    const float* kn_w     = (const float*)d_in[6];
    const float* kn_b     = (const float*)d_in[7];
    const float* relpos   = (const float*)d_in[8];
    const float* norm2_w  = (const float*)d_in[9];
    const float* out_w    = (const float*)d_in[10];
    const float* out_b    = (const float*)d_in[11];
    const float* gamma_a  = (const float*)d_in[12];
    const float* fc1_w    = (const float*)d_in[13];
    const float* fc1_b    = (const float*)d_in[14];
    const float* fc2_w    = (const float*)d_in[15];
    const float* fc2_b    = (const float*)d_in[16];
    const float* mlpn_w   = (const float*)d_in[17];
    const float* gamma_m  = (const float*)d_in[18];
    const int*   bcs      = (const int*)d_in[19];
    float* out = (float*)d_out;

    void *xn_p, *win_p, *wout_p, *wfc1_p, *wfc2_p, *attA_p, *attB_p,
         *abf_p, *x1_p, *x1bf_p, *h_p, *mb_p;
    cudaGetSymbolAddress(&xn_p,   g_xn);
    cudaGetSymbolAddress(&win_p,  g_win);
    cudaGetSymbolAddress(&wout_p, g_wout);
    cudaGetSymbolAddress(&wfc1_p, g_wfc1);
    cudaGetSymbolAddress(&wfc2_p, g_wfc2);
    cudaGetSymbolAddress(&attA_p, g_attA);
    cudaGetSymbolAddress(&attB_p, g_attB);
    cudaGetSymbolAddress(&abf_p,  g_abf);
    cudaGetSymbolAddress(&x1_p,   g_x1);
    cudaGetSymbolAddress(&x1bf_p, g_x1bf);
    cudaGetSymbolAddress(&h_p,    g_h);
    cudaGetSymbolAddress(&mb_p,   g_mb);

    cudaFuncSetAttribute(k_attn,    cudaFuncAttributeMaxDynamicSharedMemorySize, ATT_SMEM);
    cudaFuncSetAttribute(k_gemm<1>, cudaFuncAttributeMaxDynamicSharedMemorySize, GEMM_SMEM);
    cudaFuncSetAttribute(k_gemm<2>, cudaFuncAttributeMaxDynamicSharedMemorySize, GEMM_SMEM);
    cudaFuncSetAttribute(k_gemm<3>, cudaFuncAttributeMaxDynamicSharedMemorySize, GEMM_SMEM);
    cudaFuncSetAttribute(k_gemm<4>, cudaFuncAttributeMaxDynamicSharedMemorySize, GEMM_SMEM);

    const int ELW4 = (NTOK*CDIM)/4/256;

    // 1-3: norm1 stats/scale/apply (+ all weight conversions piggybacked)
    k_stats<float><<<dim3(SPA/32, BBATCH), 128>>>(x, nullptr);
    k_scale<<<4,256>>>(norm1_w, nullptr, 1e-8f);
    k_apply<float><<<ELW4,256>>>(x, nullptr, (__nv_bfloat16*)xn_p,
        in_w,  (__nv_bfloat16*)win_p,  out_w, (__nv_bfloat16*)wout_p,
        fc1_w, (__nv_bfloat16*)wfc1_p, fc2_w, (__nv_bfloat16*)wfc2_p);

    // 4: qkv projection + fused q/k LN + transpose (PROFILED SLOT)
    k_gemm<4><<<dim3(C3/GBN, NTOK/GBM), 256, GEMM_SMEM>>>((const __nv_bfloat16*)xn_p,
        (const __nv_bfloat16*)win_p, in_b, nullptr, nullptr, nullptr, nullptr,
        qn_w, qn_b, kn_w, kn_b, C3, CDIM);

    // 5: relative position bias
    k_bias<<<(2*SPA)/256, 256>>>(relpos, bcs);

    // 6: axial attention
    k_attn<<<dim3(LSEQ, BBATCH*NHEADS, 2), 256, ATT_SMEM>>>();

    // 7-9: norm2 on 0.5*(xx+xy) -> abf
    k_stats<__nv_bfloat16><<<dim3(SPA/32, BBATCH), 128>>>(
        (const __nv_bfloat16*)attA_p, (const __nv_bfloat16*)attB_p);
    k_scale<<<4,256>>>(norm2_w, nullptr, 1e-8f);
    k_apply<__nv_bfloat16><<<ELW4,256>>>((const __nv_bfloat16*)attA_p,
        (const __nv_bfloat16*)attB_p, (__nv_bfloat16*)abf_p,
        nullptr, nullptr, nullptr, nullptr, nullptr, nullptr, nullptr, nullptr);

    // 10: out projection, fused x1 = a*gamma_att + x
    k_gemm<1><<<dim3(CDIM/GBN, NTOK/GBM), 256, GEMM_SMEM>>>((const __nv_bfloat16*)abf_p,
        (const __nv_bfloat16*)wout_p, out_b, gamma_a, x,
        (float*)x1_p, (__nv_bfloat16*)x1bf_p,
        nullptr, nullptr, nullptr, nullptr, CDIM, CDIM);

    // 11: fc1 + gelu -> h
    k_gemm<2><<<dim3(CH/GBN, NTOK/GBM), 256, GEMM_SMEM>>>((const __nv_bfloat16*)x1bf_p,
        (const __nv_bfloat16*)wfc1_p, fc1_b, nullptr, nullptr,
        nullptr, (__nv_bfloat16*)h_p,
        nullptr, nullptr, nullptr, nullptr, CH, CDIM);

    // 12: fc2 -> m
    k_gemm<3><<<dim3(CDIM/GBN, NTOK/GBM), 256, GEMM_SMEM>>>((const __nv_bfloat16*)h_p,
        (const __nv_bfloat16*)wfc2_p, fc2_b, nullptr, nullptr,
        nullptr, (__nv_bfloat16*)mb_p,
        nullptr, nullptr, nullptr, nullptr, CDIM, CH);

    // 13-15: mlpn norm + final add
    k_stats<__nv_bfloat16><<<dim3(SPA/32, BBATCH), 128>>>(
        (const __nv_bfloat16*)mb_p, nullptr);
    k_scale<<<4,256>>>(mlpn_w, gamma_m, 1e-8f);
    k_final<<<ELW4,256>>>(out);
}

// round 12
// speedup vs baseline: 1.1062x; 1.1062x over previous
#include <cuda_runtime.h>
#include <cuda_fp16.h>
#include <math.h>
#include <stdint.h>

// ---------------- problem constants ----------------
#define BBATCH 2
#define LSEQ   96
#define CDIM   512
#define C3     1536
#define CH     2048
#define NHEADS 16
#define HDIM   32
#define SPA    (LSEQ*LSEQ)          // 9216
#define NTOK   (BBATCH*SPA)         // 18432
#define BC     (BBATCH*CDIM)        // 1024

// ---------------- scratch (device globals) ----------------
__device__ float   g_sum[BC];
__device__ float   g_sq[BC];
__device__ float   g_lut[BC];
__device__ __half  g_xn[NTOK*CDIM];
__device__ __half  g_win[C3*CDIM];
__device__ __half  g_wout[CDIM*CDIM];
__device__ __half  g_wfc1[CH*CDIM];
__device__ __half  g_wfc2[CDIM*CH];
__device__ __half  g_Qb[(size_t)NTOK*CDIM];   // [b*16+h][ij][d]
__device__ __half  g_Kb[(size_t)NTOK*CDIM];
__device__ __half  g_Vb[(size_t)NTOK*CDIM];
__device__ float   g_bias[2*NHEADS*SPA];
__device__ __half  g_attA[(size_t)NTOK*CDIM];
__device__ __half  g_attB[(size_t)NTOK*CDIM];
__device__ __half  g_abf[NTOK*CDIM];
__device__ float   g_x1[(size_t)NTOK*CDIM];
__device__ __half  g_x1h[NTOK*CDIM];
__device__ __half  g_h[(size_t)NTOK*CH];
__device__ __half  g_mb[(size_t)NTOK*CDIM];

// ---------------- helpers ----------------
__device__ __forceinline__ float wsum(float v){
    #pragma unroll
    for (int o = 16; o; o >>= 1) v += __shfl_xor_sync(0xffffffffu, v, o);
    return v;
}
__device__ __forceinline__ int pymod(int a, int m){
    int r = a % m; if (r && ((r < 0) != (m < 0))) r += m; return r;
}
__device__ __forceinline__ void ld4(const float* p, float v[4]){
    float4 t = *(const float4*)p; v[0]=t.x; v[1]=t.y; v[2]=t.z; v[3]=t.w;
}
__device__ __forceinline__ void ld4(const __half* p, float v[4]){
    uint2 t = *(const uint2*)p;
    float2 a = __half22float2(*(__half2*)&t.x);
    float2 b = __half22float2(*(__half2*)&t.y);
    v[0]=a.x; v[1]=a.y; v[2]=b.x; v[3]=b.y;
}
__device__ __forceinline__ uint2 pack4(float a, float b, float c, float d){
    __half2 lo = __floats2half2_rn(a, b);
    __half2 hi = __floats2half2_rn(c, d);
    uint2 r; r.x = *(uint32_t*)&lo; r.y = *(uint32_t*)&hi; return r;
}
__device__ __forceinline__ uint32_t smem_u32(const void* p){
    return (uint32_t)__cvta_generic_to_shared(p);
}
__device__ __forceinline__ void cpasync16(void* s, const void* g){
    asm volatile("cp.async.cg.shared.global [%0], [%1], 16;\n"
        :: "r"(smem_u32(s)), "l"(g));
}
__device__ __forceinline__ void cp_commit(){ asm volatile("cp.async.commit_group;\n" ::); }
__device__ __forceinline__ void ldsm_x4(uint32_t &r0, uint32_t &r1, uint32_t &r2, uint32_t &r3,
                                        uint32_t addr){
    asm volatile("ldmatrix.sync.aligned.m8n8.x4.shared.b16 {%0,%1,%2,%3}, [%4];"
        : "=r"(r0), "=r"(r1), "=r"(r2), "=r"(r3) : "r"(addr));
}
// f16 operands, f16 accumulate (GEMM)
__device__ __forceinline__ void mma_h(uint32_t c[2],
        uint32_t a0, uint32_t a1, uint32_t a2, uint32_t a3,
        uint32_t b0, uint32_t b1){
    asm volatile(
        "mma.sync.aligned.m16n8k16.row.col.f16.f16.f16.f16 "
        "{%0,%1}, {%2,%3,%4,%5}, {%6,%7}, {%0,%1};\n"
        : "+r"(c[0]), "+r"(c[1])
        : "r"(a0), "r"(a1), "r"(a2), "r"(a3), "r"(b0), "r"(b1));
}
// f16 operands, f32 accumulate (attention)
__device__ __forceinline__ void mma_f(float c[4],
        uint32_t a0, uint32_t a1, uint32_t a2, uint32_t a3,
        uint32_t b0, uint32_t b1){
    asm volatile(
        "mma.sync.aligned.m16n8k16.row.col.f32.f16.f16.f32 "
        "{%0,%1,%2,%3}, {%4,%5,%6,%7}, {%8,%9}, {%0,%1,%2,%3};\n"
        : "+f"(c[0]), "+f"(c[1]), "+f"(c[2]), "+f"(c[3])
        : "r"(a0), "r"(a1), "r"(a2), "r"(a3), "r"(b0), "r"(b1));
}
// gelu via tanh approximation
__device__ __forceinline__ float gelu_t(float v){
    float y = 0.7978845608028654f*(v + 0.044715f*v*v*v);
    float e = __expf(2.0f*y);
    float t = 1.0f - 2.0f/(e + 1.0f);
    return 0.5f*v*(1.0f + t);
}

// ---------------- per-(b,c) sum/sumsq over spatial ----------------
template<typename T>
__global__ void k_stats(const T* __restrict__ in, const T* __restrict__ in2){
    const int b  = blockIdx.y;
    const int s0 = blockIdx.x * 32;
    const int c4 = threadIdx.x * 4;
    float s[4] = {0,0,0,0}, q[4] = {0,0,0,0};
    for (int ss = 0; ss < 32; ss++){
        size_t off = ((size_t)b*SPA + s0 + ss)*CDIM + c4;
        float v[4]; ld4(in + off, v);
        if (in2){
            float w[4]; ld4(in2 + off, w);
            #pragma unroll
            for (int j=0;j<4;j++) v[j] = 0.5f*(v[j] + w[j]);
        }
        #pragma unroll
        for (int j=0;j<4;j++){ s[j] += v[j]; q[j] += v[j]*v[j]; }
    }
    #pragma unroll
    for (int j=0;j<4;j++){
        atomicAdd(&g_sum[b*CDIM + c4 + j], s[j]);
        atomicAdd(&g_sq [b*CDIM + c4 + j], q[j]);
    }
}

// ---------------- scale LUT: w*gamma/(std+eps); then reset stats ----------------
__global__ void k_scale(const float* __restrict__ w, const float* __restrict__ gamma,
                        float eps){
    int i = blockIdx.x*256 + threadIdx.x;
    if (i < BC){
        int c = i & (CDIM-1);
        float s = g_sum[i], q = g_sq[i];
        float var = (q - s*s*(1.0f/(float)SPA)) * (1.0f/(float)(SPA-1));
        float stdv = sqrtf(fmaxf(var, 0.f));
        float g = gamma ? gamma[c] : 1.0f;
        g_lut[i] = w[c]*g/(stdv + eps);
        g_sum[i] = 0.f;
        g_sq[i]  = 0.f;
    }
}

// rms-inorm apply via LUT -> f16; optional 0.5*(A+B); optional weight conversion
template<typename T>
__global__ void k_apply(const T* __restrict__ in, const T* __restrict__ in2,
                        __half* __restrict__ outb,
                        const float* __restrict__ cw0, __half* __restrict__ cd0,
                        const float* __restrict__ cw1, __half* __restrict__ cd1,
                        const float* __restrict__ cw2, __half* __restrict__ cd2,
                        const float* __restrict__ cw3, __half* __restrict__ cd3){
    size_t i4  = (size_t)blockIdx.x*256 + threadIdx.x;
    size_t ele = i4*4;
    int c = (int)(ele & (CDIM-1));
    int b = (int)(ele / ((size_t)SPA*CDIM));
    float v[4]; ld4(in + ele, v);
    if (in2){
        float u[4]; ld4(in2 + ele, u);
        #pragma unroll
        for (int j=0;j<4;j++) v[j] = 0.5f*(v[j] + u[j]);
    }
    float4 sc = *(const float4*)(g_lut + b*CDIM + c);
    ((uint2*)outb)[i4] = pack4(v[0]*sc.x, v[1]*sc.y, v[2]*sc.z, v[3]*sc.w);

    if (cw0){
        int blk = blockIdx.x;
        const float* src = nullptr; __half* dst = nullptr; int off = 0;
        if      (blk < 768)  { src = cw0; dst = cd0; off = blk; }
        else if (blk < 1024) { src = cw1; dst = cd1; off = blk - 768; }
        else if (blk < 2048) { src = cw2; dst = cd2; off = blk - 1024; }
        else if (blk < 3072) { src = cw3; dst = cd3; off = blk - 2048; }
        if (src){
            int wi = off*256 + threadIdx.x;
            float4 t = ((const float4*)src)[wi];
            ((uint2*)dst)[wi] = pack4(t.x, t.y, t.z, t.w);
        }
    }
}

// final: out = x1 + m*lut
__global__ void k_final(float* __restrict__ out){
    size_t i4  = (size_t)blockIdx.x*256 + threadIdx.x;
    size_t ele = i4*4;
    int c = (int)(ele & (CDIM-1));
    int b = (int)(ele / ((size_t)SPA*CDIM));
    float m[4]; ld4(g_mb + ele, m);
    float4 x1 = *(const float4*)(g_x1 + ele);
    float4 sc = *(const float4*)(g_lut + b*CDIM + c);
    float4 r;
    r.x = x1.x + m[0]*sc.x;
    r.y = x1.y + m[1]*sc.y;
    r.z = x1.z + m[2]*sc.z;
    r.w = x1.w + m[3]*sc.w;
    *(float4*)(out + ele) = r;
}

// ---------------- f16 mma GEMM: 128x128x32, 4-stage cp.async, f16 accum --------
// C[M,N] = A[M,K] * B[N,K]^T
#define GBM 128
#define GBN 128
#define GBK 32
#define GSTR 40
#define GSLOT ((GBM+GBN)*GSTR)          // 10240 elems per stage
#define GEMM_SMEM (4*GSLOT*2)           // 81920 bytes
#define TSTR 132                        // f32 epilogue tile stride (MODE 4)

// MODE 1: y=(acc+bias)*gamma+res -> Cf f32 + Cb f16
// MODE 2: Cb = f16(gelu(acc+bias))
// MODE 3: Cb = f16(acc+bias)
// MODE 4: qkv epilogue: per-segment q/k LayerNorm + transpose into g_Qb/g_Kb/g_Vb
template<int MODE>
__global__ void __launch_bounds__(256,2) k_gemm(
        const __half* __restrict__ A, const __half* __restrict__ Bw,
        const float* __restrict__ bias, const float* __restrict__ gamma,
        const float* __restrict__ res,
        float* __restrict__ Cf, __half* __restrict__ Cb,
        const float* __restrict__ qw, const float* __restrict__ qb,
        const float* __restrict__ kw, const float* __restrict__ kb,
        int Nn, int K){
    extern __shared__ __half smg[];
    const int tid  = threadIdx.x;
    const int lane = tid & 31, warp = tid >> 5;
    const int gid  = lane >> 2, tig = lane & 3;
    const int wm   = warp >> 2, wn  = warp & 3;
    const int bm   = blockIdx.y * GBM;
    const int bn   = blockIdx.x * GBN;

    const int aRow    = wm*64 + ((lane>>3)&1)*8 + (lane&7);
    const int aColOff = (lane>>4)*8;
    const int bRow    = wn*32 + ((lane>>4)&1)*8 + (lane&7);
    const int bColOff = ((lane>>3)&1)*8;

    uint32_t acc[4][4][2];
    #pragma unroll
    for (int mi=0; mi<4; mi++)
        #pragma unroll
        for (int ni=0; ni<4; ni++){ acc[mi][ni][0] = 0u; acc[mi][ni][1] = 0u; }

    auto load_stage = [&](int s, int k0){
        __half* dA = smg + s*GSLOT;
        __half* dB = dA + GBM*GSTR;
        #pragma unroll
        for (int r = 0; r < 2; r++){
            int idx = tid + r*256;
            int row = idx >> 2;
            int cv  = (idx & 3) << 3;
            cpasync16(dA + row*GSTR + cv, A  + (size_t)(bm+row)*K + k0 + cv);
            cpasync16(dB + row*GSTR + cv, Bw + (size_t)(bn+row)*K + k0 + cv);
        }
    };

    const int T = K >> 5;
    load_stage(0, 0);  cp_commit();
    load_stage(1, 32); cp_commit();

    for (int it = 0; it < T; it++){
        if (it + 2 < T) load_stage((it+2)&3, (it+2) << 5);
        cp_commit();
        asm volatile("cp.async.wait_group 2;" ::: "memory");
        __syncthreads();
        const __half* sA = smg + (it&3)*GSLOT;
        const __half* sB = sA + GBM*GSTR;
        #pragma unroll
        for (int kk = 0; kk < GBK; kk += 16){
            uint32_t af[4][4], bfr[4][2];
            #pragma unroll
            for (int mi=0; mi<4; mi++){
                uint32_t addr = smem_u32(sA + (aRow + mi*16)*GSTR + kk + aColOff);
                ldsm_x4(af[mi][0], af[mi][1], af[mi][2], af[mi][3], addr);
            }
            #pragma unroll
            for (int np=0; np<2; np++){
                uint32_t addr = smem_u32(sB + (bRow + np*16)*GSTR + kk + bColOff);
                ldsm_x4(bfr[2*np][0], bfr[2*np][1], bfr[2*np+1][0], bfr[2*np+1][1], addr);
            }
            #pragma unroll
            for (int mi=0; mi<4; mi++)
                #pragma unroll
                for (int ni=0; ni<4; ni++)
                    mma_h(acc[mi][ni], af[mi][0], af[mi][1], af[mi][2], af[mi][3],
                          bfr[ni][0], bfr[ni][1]);
        }
    }

    if (MODE == 4){
        // ---- fused q/k LayerNorm + head transpose epilogue ----
        float* sT = (float*)smg;                                 // 128 x TSTR f32
        __half* sStage = (__half*)((char*)smg + 128*TSTR*4);     // 128x32 f16
        __syncthreads();
        #pragma unroll
        for (int mi=0; mi<4; mi++){
            int r0 = wm*64 + mi*16 + gid;
            #pragma unroll
            for (int ni=0; ni<4; ni++){
                int c = wn*32 + ni*8 + tig*2;
                float b0 = bias[bn + c], b1 = bias[bn + c + 1];
                float2 lo = __half22float2(*(__half2*)&acc[mi][ni][0]);
                float2 hi = __half22float2(*(__half2*)&acc[mi][ni][1]);
                *(float2*)(sT + r0*TSTR + c)     = make_float2(lo.x+b0, lo.y+b1);
                *(float2*)(sT + (r0+8)*TSTR + c) = make_float2(hi.x+b0, hi.y+b1);
            }
        }
        __syncthreads();
        const int b   = bm / SPA;
        const int ij0 = bm % SPA;
        #pragma unroll
        for (int seg = 0; seg < 4; seg++){
            int segidx = (bn >> 5) + seg;
            int t = segidx % 3, h = segidx / 3;
            const float* lw = (t == 0) ? qw : kw;
            const float* lb = (t == 0) ? qb : kb;
            float wv = (t < 2) ? lw[lane] : 0.f;
            float bv = (t < 2) ? lb[lane] : 0.f;
            for (int rr = 0; rr < 16; rr++){
                int row = warp*16 + rr;
                float val = sT[row*TSTR + seg*32 + lane];
                if (t < 2){
                    float mu = wsum(val) * (1.f/32.f);
                    float d  = val - mu;
                    float vr = wsum(d*d) * (1.f/32.f);
                    val = d * rsqrtf(vr + 1e-5f) * wv + bv;
                }
                sStage[row*32 + lane] = __float2half(val);
            }
            __syncthreads();
            __half* dst = ((t == 0) ? g_Qb : (t == 1) ? g_Kb : g_Vb)
                          + ((size_t)(b*NHEADS + h)*SPA + ij0)*HDIM;
            #pragma unroll
            for (int i = tid; i < 512; i += 256)
                ((uint4*)dst)[i] = ((const uint4*)sStage)[i];
            __syncthreads();
        }
        return;
    }

    // standard epilogues
    #pragma unroll
    for (int mi=0; mi<4; mi++){
        int r0 = bm + wm*64 + mi*16 + gid;
        #pragma unroll
        for (int ni=0; ni<4; ni++){
            int c = bn + wn*32 + ni*8 + tig*2;
            float2 lo = __half22float2(*(__half2*)&acc[mi][ni][0]);
            float2 hi = __half22float2(*(__half2*)&acc[mi][ni][1]);
            #pragma unroll
            for (int half2i=0; half2i<2; half2i++){
                int r = r0 + half2i*8;
                float v0 = (half2i ? hi.x : lo.x) + bias[c];
                float v1 = (half2i ? hi.y : lo.y) + bias[c+1];
                size_t o = (size_t)r*Nn + c;
                if (MODE == 1){
                    float y0 = v0*gamma[c]   + res[o];
                    float y1 = v1*gamma[c+1] + res[o+1];
                    *(float2*)(Cf + o) = make_float2(y0, y1);
                    __half2 t = __floats2half2_rn(y0, y1);
                    *(__half2*)(Cb + o) = t;
                } else if (MODE == 2){
                    __half2 t = __floats2half2_rn(gelu_t(v0), gelu_t(v1));
                    *(__half2*)(Cb + o) = t;
                } else {
                    __half2 t = __floats2half2_rn(v0, v1);
                    *(__half2*)(Cb + o) = t;
                }
            }
        }
    }
}

// ---------------- T5 relative position bias ----------------
__global__ void k_bias(const float* __restrict__ emb, const int* __restrict__ bcs){
    int idx = blockIdx.x*256 + threadIdx.x;
    int dir = idx / SPA;
    int qk  = idx % SPA;
    int q = qk / LSEQ, kk = qk % LSEQ;
    int bc = bcs[dir];
    int rel = kk - q;
    if (bc == 1){
        const int thr = LSEQ/2;
        if      (rel < -thr) rel = pymod(rel,  thr);
        else if (rel >  thr) rel = pymod(rel, -thr);
    }
    int n = -rel;
    int ret = (n < 0) ? 16 : 0;
    n = (n < 0) ? -n : n;
    int bucket;
    if (n < 8) bucket = ret + n;
    else {
        int vl = 8 + (int)(logf((float)n * 0.125f) / logf(4.0f) * 8.0f);
        if (vl > 15) vl = 15;
        bucket = ret + vl;
    }
    #pragma unroll
    for (int h = 0; h < NHEADS; h++)
        g_bias[(dir*NHEADS + h)*SPA + qk] = emb[bucket*NHEADS + h];
}

// ---------------- tensor-core axial attention (f16 operands, f32 acc) ----------
#define AQSTR 40
#define AVSTR 106
#define ASSTR 100
#define APSTR 104
#define OFF_K  (96*AQSTR)
#define OFF_VT (2*96*AQSTR)
#define OFF_S_BYTES  ((2*96*AQSTR + 32*AVSTR)*2)
#define OFF_P_BYTES  (OFF_S_BYTES + 96*ASSTR*4)
#define ATT_SMEM (OFF_P_BYTES + 96*APSTR*2)

__global__ void __launch_bounds__(256,2) k_attn(){
    extern __shared__ char smraw[];
    __half* sQ  = (__half*)smraw;
    __half* sK  = sQ + OFF_K;
    __half* sVt = sQ + OFF_VT;
    float*  sS  = (float*)(smraw + OFF_S_BYTES);
    __half* sP  = (__half*)(smraw + OFF_P_BYTES);

    const int line = blockIdx.x;
    const int bh   = blockIdx.y;
    const int dir  = blockIdx.z;
    const int head = bh & (NHEADS-1);
    const int bidx = bh >> 4;
    const int tid  = threadIdx.x;
    const int lane = tid & 31, warp = tid >> 5;
    const int gid  = lane >> 2, tig = lane & 3;
    const int wm   = warp >> 2, wn  = warp & 3;
    const size_t base = (size_t)bh * SPA * HDIM;

    for (int u = tid; u < 1536; u += 256){
        int row = u >> 4;
        int dp  = (u & 15) << 1;
        size_t g = base + dp + (size_t)HDIM * (dir == 0 ? (line*LSEQ + row)
                                                        : (row*LSEQ + line));
        *(uint32_t*)(sQ + row*AQSTR + dp) = *(const uint32_t*)(g_Qb + g);
        *(uint32_t*)(sK + row*AQSTR + dp) = *(const uint32_t*)(g_Kb + g);
        uint32_t vv = *(const uint32_t*)(g_Vb + g);
        __half2 v2 = *(__half2*)&vv;
        sVt[dp*AVSTR + row]     = v2.x;
        sVt[(dp+1)*AVSTR + row] = v2.y;
    }
    __syncthreads();

    {
        float acc[3][3][4];
        #pragma unroll
        for (int mi=0;mi<3;mi++)
            #pragma unroll
            for (int ni=0;ni<3;ni++)
                #pragma unroll
                for (int e=0;e<4;e++) acc[mi][ni][e] = 0.f;
        #pragma unroll
        for (int ks=0; ks<2; ks++){
            int kk = ks*16;
            uint32_t af[3][4], bfr[3][2];
            #pragma unroll
            for (int mi=0;mi<3;mi++){
                const __half* p = sQ + (wm*48 + mi*16 + gid)*AQSTR + kk + tig*2;
                af[mi][0] = *(const uint32_t*)p;
                af[mi][1] = *(const uint32_t*)(p + 8*AQSTR);
                af[mi][2] = *(const uint32_t*)(p + 8);
                af[mi][3] = *(const uint32_t*)(p + 8*AQSTR + 8);
            }
            #pragma unroll
            for (int ni=0;ni<3;ni++){
                const __half* p = sK + (wn*24 + ni*8 + gid)*AQSTR + kk + tig*2;
                bfr[ni][0] = *(const uint32_t*)p;
                bfr[ni][1] = *(const uint32_t*)(p + 8);
            }
            #pragma unroll
            for (int mi=0;mi<3;mi++)
                #pragma unroll
                for (int ni=0;ni<3;ni++)
                    mma_f(acc[mi][ni], af[mi][0], af[mi][1], af[mi][2], af[mi][3],
                          bfr[ni][0], bfr[ni][1]);
        }
        const float* bb = g_bias + (size_t)(dir*NHEADS + head)*SPA;
        const float SC = 0.17677669529663687f;
        #pragma unroll
        for (int mi=0;mi<3;mi++){
            int r = wm*48 + mi*16 + gid;
            #pragma unroll
            for (int ni=0;ni<3;ni++){
                int c = wn*24 + ni*8 + tig*2;
                sS[r*ASSTR + c]       = acc[mi][ni][0]*SC + bb[r*LSEQ + c];
                sS[r*ASSTR + c+1]     = acc[mi][ni][1]*SC + bb[r*LSEQ + c+1];
                sS[(r+8)*ASSTR + c]   = acc[mi][ni][2]*SC + bb[(r+8)*LSEQ + c];
                sS[(r+8)*ASSTR + c+1] = acc[mi][ni][3]*SC + bb[(r+8)*LSEQ + c+1];
            }
        }
    }
    __syncthreads();

    for (int r = warp; r < LSEQ; r += 8){
        const float* row = sS + r*ASSTR;
        float v0 = row[lane], v1 = row[lane+32], v2 = row[lane+64];
        float m = fmaxf(v0, fmaxf(v1, v2));
        #pragma unroll
        for (int o = 16; o; o >>= 1) m = fmaxf(m, __shfl_xor_sync(0xffffffffu, m, o));
        float e0 = __expf(v0 - m), e1 = __expf(v1 - m), e2 = __expf(v2 - m);
        float s = e0 + e1 + e2;
        #pragma unroll
        for (int o = 16; o; o >>= 1) s += __shfl_xor_sync(0xffffffffu, s, o);
        float inv = 1.0f / s;
        __half* pr = sP + r*APSTR;
        pr[lane]    = __float2half(e0*inv);
        pr[lane+32] = __float2half(e1*inv);
        pr[lane+64] = __float2half(e2*inv);
    }
    __syncthreads();

    {
        float po[3][4];
        #pragma unroll
        for (int mi=0;mi<3;mi++)
            #pragma unroll
            for (int e=0;e<4;e++) po[mi][e] = 0.f;
        #pragma unroll
        for (int ks=0; ks<6; ks++){
            int kk = ks*16;
            uint32_t b0 = *(const uint32_t*)(sVt + (wn*8 + gid)*AVSTR + kk + tig*2);
            uint32_t b1 = *(const uint32_t*)(sVt + (wn*8 + gid)*AVSTR + kk + 8 + tig*2);
            #pragma unroll
            for (int mi=0;mi<3;mi++){
                const __half* p = sP + (wm*48 + mi*16 + gid)*APSTR + kk + tig*2;
                uint32_t a0 = *(const uint32_t*)p;
                uint32_t a1 = *(const uint32_t*)(p + 8*APSTR);
                uint32_t a2 = *(const uint32_t*)(p + 8);
                uint32_t a3 = *(const uint32_t*)(p + 8*APSTR + 8);
                mma_f(po[mi], a0, a1, a2, a3, b0, b1);
            }
        }
        __half* outp = dir ? g_attB : g_attA;
        int d = wn*8 + tig*2;
        #pragma unroll
        for (int mi=0;mi<3;mi++){
            int r = wm*48 + mi*16 + gid;
            #pragma unroll
            for (int hf=0; hf<2; hf++){
                int q = r + hf*8;
                int token = (dir == 0) ? ((bidx*LSEQ + line)*LSEQ + q)
                                       : ((bidx*LSEQ + q)*LSEQ + line);
                __half2 t = __floats2half2_rn(po[mi][hf*2], po[mi][hf*2+1]);
                *(__half2*)(outp + (size_t)token*CDIM + head*HDIM + d) = t;
            }
        }
    }
}

// ---------------- launch ----------------
extern "C" void kernel_launch(void* const* d_in, const int* in_sizes, int n_in,
                              void* d_out, int out_size){
    const float* x        = (const float*)d_in[0];
    const float* norm1_w  = (const float*)d_in[1];
    const float* in_w     = (const float*)d_in[2];
    const float* in_b     = (const float*)d_in[3];
    const float* qn_w     = (const float*)d_in[4];
    const float* qn_b     = (const float*)d_in[5];
    const float* kn_w     = (const float*)d_in[6];
    const float* kn_b     = (const float*)d_in[7];
    const float* relpos   = (const float*)d_in[8];
    const float* norm2_w  = (const float*)d_in[9];
    const float* out_w    = (const float*)d_in[10];
    const float* out_b    = (const float*)d_in[11];
    const float* gamma_a  = (const float*)d_in[12];
    const float* fc1_w    = (const float*)d_in[13];
    const float* fc1_b    = (const float*)d_in[14];
    const float* fc2_w    = (const float*)d_in[15];
    const float* fc2_b    = (const float*)d_in[16];
    const float* mlpn_w   = (const float*)d_in[17];
    const float* gamma_m  = (const float*)d_in[18];
    const int*   bcs      = (const int*)d_in[19];
    float* out = (float*)d_out;

    void *xn_p, *win_p, *wout_p, *wfc1_p, *wfc2_p, *attA_p, *attB_p,
         *abf_p, *x1_p, *x1h_p, *h_p, *mb_p;
    cudaGetSymbolAddress(&xn_p,   g_xn);
    cudaGetSymbolAddress(&win_p,  g_win);
    cudaGetSymbolAddress(&wout_p, g_wout);
    cudaGetSymbolAddress(&wfc1_p, g_wfc1);
    cudaGetSymbolAddress(&wfc2_p, g_wfc2);
    cudaGetSymbolAddress(&attA_p, g_attA);
    cudaGetSymbolAddress(&attB_p, g_attB);
    cudaGetSymbolAddress(&abf_p,  g_abf);
    cudaGetSymbolAddress(&x1_p,   g_x1);
    cudaGetSymbolAddress(&x1h_p,  g_x1h);
    cudaGetSymbolAddress(&h_p,    g_h);
    cudaGetSymbolAddress(&mb_p,   g_mb);

    cudaFuncSetAttribute(k_attn,    cudaFuncAttributeMaxDynamicSharedMemorySize, ATT_SMEM);
    cudaFuncSetAttribute(k_gemm<1>, cudaFuncAttributeMaxDynamicSharedMemorySize, GEMM_SMEM);
    cudaFuncSetAttribute(k_gemm<2>, cudaFuncAttributeMaxDynamicSharedMemorySize, GEMM_SMEM);
    cudaFuncSetAttribute(k_gemm<3>, cudaFuncAttributeMaxDynamicSharedMemorySize, GEMM_SMEM);
    cudaFuncSetAttribute(k_gemm<4>, cudaFuncAttributeMaxDynamicSharedMemorySize, GEMM_SMEM);

    const int ELW4 = (NTOK*CDIM)/4/256;

    // 1-3: norm1 stats/scale/apply (+ all weight conversions piggybacked)
    k_stats<float><<<dim3(SPA/32, BBATCH), 128>>>(x, nullptr);
    k_scale<<<4,256>>>(norm1_w, nullptr, 1e-8f);
    k_apply<float><<<ELW4,256>>>(x, nullptr, (__half*)xn_p,
        in_w,  (__half*)win_p,  out_w, (__half*)wout_p,
        fc1_w, (__half*)wfc1_p, fc2_w, (__half*)wfc2_p);

    // 4: qkv projection + fused q/k LN + transpose (PROFILED SLOT)
    k_gemm<4><<<dim3(C3/GBN, NTOK/GBM), 256, GEMM_SMEM>>>((const __half*)xn_p,
        (const __half*)win_p, in_b, nullptr, nullptr, nullptr, nullptr,
        qn_w, qn_b, kn_w, kn_b, C3, CDIM);

    // 5: relative position bias
    k_bias<<<(2*SPA)/256, 256>>>(relpos, bcs);

    // 6: axial attention
    k_attn<<<dim3(LSEQ, BBATCH*NHEADS, 2), 256, ATT_SMEM>>>();

    // 7-9: norm2 on 0.5*(xx+xy) -> abf
    k_stats<__half><<<dim3(SPA/32, BBATCH), 128>>>(
        (const __half*)attA_p, (const __half*)attB_p);
    k_scale<<<4,256>>>(norm2_w, nullptr, 1e-8f);
    k_apply<__half><<<ELW4,256>>>((const __half*)attA_p,
        (const __half*)attB_p, (__half*)abf_p,
        nullptr, nullptr, nullptr, nullptr, nullptr, nullptr, nullptr, nullptr);

    // 10: out projection, fused x1 = a*gamma_att + x
    k_gemm<1><<<dim3(CDIM/GBN, NTOK/GBM), 256, GEMM_SMEM>>>((const __half*)abf_p,
        (const __half*)wout_p, out_b, gamma_a, x,
        (float*)x1_p, (__half*)x1h_p,
        nullptr, nullptr, nullptr, nullptr, CDIM, CDIM);

    // 11: fc1 + gelu -> h
    k_gemm<2><<<dim3(CH/GBN, NTOK/GBM), 256, GEMM_SMEM>>>((const __half*)x1h_p,
        (const __half*)wfc1_p, fc1_b, nullptr, nullptr,
        nullptr, (__half*)h_p,
        nullptr, nullptr, nullptr, nullptr, CH, CDIM);

    // 12: fc2 -> m
    k_gemm<3><<<dim3(CDIM/GBN, NTOK/GBM), 256, GEMM_SMEM>>>((const __half*)h_p,
        (const __half*)wfc2_p, fc2_b, nullptr, nullptr,
        nullptr, (__half*)mb_p,
        nullptr, nullptr, nullptr, nullptr, CDIM, CH);

    // 13-15: mlpn norm + final add
    k_stats<__half><<<dim3(SPA/32, BBATCH), 128>>>(
        (const __half*)mb_p, nullptr);
    k_scale<<<4,256>>>(mlpn_w, gamma_m, 1e-8f);
    k_final<<<ELW4,256>>>(out);
}

// round 16
// speedup vs baseline: 1.1534x; 1.0427x over previous
#include <cuda_runtime.h>
#include <cuda_fp16.h>
#include <math.h>
#include <stdint.h>

// ---------------- problem constants ----------------
#define BBATCH 2
#define LSEQ   96
#define CDIM   512
#define C3     1536
#define CH     2048
#define NHEADS 16
#define HDIM   32
#define SPA    (LSEQ*LSEQ)          // 9216
#define NTOK   (BBATCH*SPA)         // 18432
#define BC     (BBATCH*CDIM)        // 1024

// ---------------- scratch (device globals) ----------------
__device__ float   g_sum[BC];
__device__ float   g_sq[BC];
__device__ float   g_lut[BC];
__device__ __half  g_xn[NTOK*CDIM];
__device__ __half  g_win[C3*CDIM];
__device__ __half  g_wout[CDIM*CDIM];
__device__ __half  g_wfc1[CH*CDIM];
__device__ __half  g_wfc2[CDIM*CH];
__device__ __half  g_Qb[(size_t)NTOK*CDIM];   // [b*16+h][ij][d]
__device__ __half  g_Kb[(size_t)NTOK*CDIM];
__device__ __half  g_Vb[(size_t)NTOK*CDIM];
__device__ float   g_bias[2*NHEADS*SPA];
__device__ __half  g_attA[(size_t)NTOK*CDIM];
__device__ __half  g_attB[(size_t)NTOK*CDIM];
__device__ __half  g_abf[NTOK*CDIM];
__device__ float   g_x1[(size_t)NTOK*CDIM];
__device__ __half  g_x1h[NTOK*CDIM];
__device__ __half  g_h[(size_t)NTOK*CH];
__device__ __half  g_mb[(size_t)NTOK*CDIM];

// ---------------- helpers ----------------
__device__ __forceinline__ float wsum(float v){
    #pragma unroll
    for (int o = 16; o; o >>= 1) v += __shfl_xor_sync(0xffffffffu, v, o);
    return v;
}
__device__ __forceinline__ int pymod(int a, int m){
    int r = a % m; if (r && ((r < 0) != (m < 0))) r += m; return r;
}
__device__ __forceinline__ void ld4(const float* p, float v[4]){
    float4 t = *(const float4*)p; v[0]=t.x; v[1]=t.y; v[2]=t.z; v[3]=t.w;
}
__device__ __forceinline__ void ld4(const __half* p, float v[4]){
    uint2 t = *(const uint2*)p;
    float2 a = __half22float2(*(__half2*)&t.x);
    float2 b = __half22float2(*(__half2*)&t.y);
    v[0]=a.x; v[1]=a.y; v[2]=b.x; v[3]=b.y;
}
__device__ __forceinline__ uint2 pack4(float a, float b, float c, float d){
    __half2 lo = __floats2half2_rn(a, b);
    __half2 hi = __floats2half2_rn(c, d);
    uint2 r; r.x = *(uint32_t*)&lo; r.y = *(uint32_t*)&hi; return r;
}
__device__ __forceinline__ uint32_t smem_u32(const void* p){
    return (uint32_t)__cvta_generic_to_shared(p);
}
__device__ __forceinline__ void cpasync16(void* s, const void* g){
    asm volatile("cp.async.cg.shared.global [%0], [%1], 16;\n"
        :: "r"(smem_u32(s)), "l"(g));
}
__device__ __forceinline__ void cp_commit(){ asm volatile("cp.async.commit_group;\n" ::); }
__device__ __forceinline__ void ldsm_x4(uint32_t &r0, uint32_t &r1, uint32_t &r2, uint32_t &r3,
                                        uint32_t addr){
    asm volatile("ldmatrix.sync.aligned.m8n8.x4.shared.b16 {%0,%1,%2,%3}, [%4];"
        : "=r"(r0), "=r"(r1), "=r"(r2), "=r"(r3) : "r"(addr));
}
// f16 operands, f16 accumulate (GEMM)
__device__ __forceinline__ void mma_h(uint32_t c[2],
        uint32_t a0, uint32_t a1, uint32_t a2, uint32_t a3,
        uint32_t b0, uint32_t b1){
    asm volatile(
        "mma.sync.aligned.m16n8k16.row.col.f16.f16.f16.f16 "
        "{%0,%1}, {%2,%3,%4,%5}, {%6,%7}, {%0,%1};\n"
        : "+r"(c[0]), "+r"(c[1])
        : "r"(a0), "r"(a1), "r"(a2), "r"(a3), "r"(b0), "r"(b1));
}
// f16 operands, f32 accumulate (attention)
__device__ __forceinline__ void mma_f(float c[4],
        uint32_t a0, uint32_t a1, uint32_t a2, uint32_t a3,
        uint32_t b0, uint32_t b1){
    asm volatile(
        "mma.sync.aligned.m16n8k16.row.col.f32.f16.f16.f32 "
        "{%0,%1,%2,%3}, {%4,%5,%6,%7}, {%8,%9}, {%0,%1,%2,%3};\n"
        : "+f"(c[0]), "+f"(c[1]), "+f"(c[2]), "+f"(c[3])
        : "r"(a0), "r"(a1), "r"(a2), "r"(a3), "r"(b0), "r"(b1));
}
// gelu via tanh approximation
__device__ __forceinline__ float gelu_t(float v){
    float y = 0.7978845608028654f*(v + 0.044715f*v*v*v);
    float e = __expf(2.0f*y);
    float t = 1.0f - 2.0f/(e + 1.0f);
    return 0.5f*v*(1.0f + t);
}

// ---------------- per-(b,c) sum/sumsq over spatial ----------------
template<typename T>
__global__ void k_stats(const T* __restrict__ in, const T* __restrict__ in2){
    const int b  = blockIdx.y;
    const int s0 = blockIdx.x * 32;
    const int c4 = threadIdx.x * 4;
    float s[4] = {0,0,0,0}, q[4] = {0,0,0,0};
    for (int ss = 0; ss < 32; ss++){
        size_t off = ((size_t)b*SPA + s0 + ss)*CDIM + c4;
        float v[4]; ld4(in + off, v);
        if (in2){
            float w[4]; ld4(in2 + off, w);
            #pragma unroll
            for (int j=0;j<4;j++) v[j] = 0.5f*(v[j] + w[j]);
        }
        #pragma unroll
        for (int j=0;j<4;j++){ s[j] += v[j]; q[j] += v[j]*v[j]; }
    }
    #pragma unroll
    for (int j=0;j<4;j++){
        atomicAdd(&g_sum[b*CDIM + c4 + j], s[j]);
        atomicAdd(&g_sq [b*CDIM + c4 + j], q[j]);
    }
}

// ---------------- scale LUT: w*gamma/(std+eps); then reset stats ----------------
__global__ void k_scale(const float* __restrict__ w, const float* __restrict__ gamma,
                        float eps){
    int i = blockIdx.x*256 + threadIdx.x;
    if (i < BC){
        int c = i & (CDIM-1);
        float s = g_sum[i], q = g_sq[i];
        float var = (q - s*s*(1.0f/(float)SPA)) * (1.0f/(float)(SPA-1));
        float stdv = sqrtf(fmaxf(var, 0.f));
        float g = gamma ? gamma[c] : 1.0f;
        g_lut[i] = w[c]*g/(stdv + eps);
        g_sum[i] = 0.f;
        g_sq[i]  = 0.f;
    }
}

// rms-inorm apply via LUT -> f16; optional 0.5*(A+B); optional weight conversion
template<typename T>
__global__ void k_apply(const T* __restrict__ in, const T* __restrict__ in2,
                        __half* __restrict__ outb,
                        const float* __restrict__ cw0, __half* __restrict__ cd0,
                        const float* __restrict__ cw1, __half* __restrict__ cd1,
                        const float* __restrict__ cw2, __half* __restrict__ cd2,
                        const float* __restrict__ cw3, __half* __restrict__ cd3){
    size_t i4  = (size_t)blockIdx.x*256 + threadIdx.x;
    size_t ele = i4*4;
    int c = (int)(ele & (CDIM-1));
    int b = (int)(ele / ((size_t)SPA*CDIM));
    float v[4]; ld4(in + ele, v);
    if (in2){
        float u[4]; ld4(in2 + ele, u);
        #pragma unroll
        for (int j=0;j<4;j++) v[j] = 0.5f*(v[j] + u[j]);
    }
    float4 sc = *(const float4*)(g_lut + b*CDIM + c);
    ((uint2*)outb)[i4] = pack4(v[0]*sc.x, v[1]*sc.y, v[2]*sc.z, v[3]*sc.w);

    if (cw0){
        int blk = blockIdx.x;
        const float* src = nullptr; __half* dst = nullptr; int off = 0;
        if      (blk < 768)  { src = cw0; dst = cd0; off = blk; }
        else if (blk < 1024) { src = cw1; dst = cd1; off = blk - 768; }
        else if (blk < 2048) { src = cw2; dst = cd2; off = blk - 1024; }
        else if (blk < 3072) { src = cw3; dst = cd3; off = blk - 2048; }
        if (src){
            int wi = off*256 + threadIdx.x;
            float4 t = ((const float4*)src)[wi];
            ((uint2*)dst)[wi] = pack4(t.x, t.y, t.z, t.w);
        }
    }
}

// final: out = x1 + m*lut
__global__ void k_final(float* __restrict__ out){
    size_t i4  = (size_t)blockIdx.x*256 + threadIdx.x;
    size_t ele = i4*4;
    int c = (int)(ele & (CDIM-1));
    int b = (int)(ele / ((size_t)SPA*CDIM));
    float m[4]; ld4(g_mb + ele, m);
    float4 x1 = *(const float4*)(g_x1 + ele);
    float4 sc = *(const float4*)(g_lut + b*CDIM + c);
    float4 r;
    r.x = x1.x + m[0]*sc.x;
    r.y = x1.y + m[1]*sc.y;
    r.z = x1.z + m[2]*sc.z;
    r.w = x1.w + m[3]*sc.w;
    *(float4*)(out + ele) = r;
}

// ---------------- f16 mma GEMM: 128x128x32, 3-stage cp.async, 3 CTAs/SM --------
// C[M,N] = A[M,K] * B[N,K]^T
#define GBM 128
#define GBN 128
#define GBK 32
#define GSTR 40
#define GSLOT ((GBM+GBN)*GSTR)          // 10240 elems per stage
#define GEMM_SMEM (3*GSLOT*2)           // 61440 bytes
#define TSTR_H 136                      // f16 epilogue tile stride (MODE 4)

// MODE 1: y=(acc+bias)*gamma+res -> Cf f32 + Cb f16
// MODE 2: Cb = f16(gelu(acc+bias))
// MODE 3: Cb = f16(acc+bias)
// MODE 4: qkv epilogue: per-segment q/k LayerNorm + transpose into g_Qb/g_Kb/g_Vb
template<int MODE>
__global__ void __launch_bounds__(256,3) k_gemm(
        const __half* __restrict__ A, const __half* __restrict__ Bw,
        const float* __restrict__ bias, const float* __restrict__ gamma,
        const float* __restrict__ res,
        float* __restrict__ Cf, __half* __restrict__ Cb,
        const float* __restrict__ qw, const float* __restrict__ qb,
        const float* __restrict__ kw, const float* __restrict__ kb,
        int Nn, int K){
    extern __shared__ __half smg[];
    const int tid  = threadIdx.x;
    const int lane = tid & 31, warp = tid >> 5;
    const int gid  = lane >> 2, tig = lane & 3;
    const int wm   = warp >> 2, wn  = warp & 3;
    const int bm   = blockIdx.y * GBM;
    const int bn   = blockIdx.x * GBN;

    const int aRow    = wm*64 + ((lane>>3)&1)*8 + (lane&7);
    const int aColOff = (lane>>4)*8;
    const int bRow    = wn*32 + ((lane>>4)&1)*8 + (lane&7);
    const int bColOff = ((lane>>3)&1)*8;

    uint32_t acc[4][4][2];
    #pragma unroll
    for (int mi=0; mi<4; mi++)
        #pragma unroll
        for (int ni=0; ni<4; ni++){ acc[mi][ni][0] = 0u; acc[mi][ni][1] = 0u; }

    auto load_stage = [&](int s, int k0){
        __half* dA = smg + s*GSLOT;
        __half* dB = dA + GBM*GSTR;
        #pragma unroll
        for (int r = 0; r < 2; r++){
            int idx = tid + r*256;
            int row = idx >> 2;
            int cv  = (idx & 3) << 3;
            cpasync16(dA + row*GSTR + cv, A  + (size_t)(bm+row)*K + k0 + cv);
            cpasync16(dB + row*GSTR + cv, Bw + (size_t)(bn+row)*K + k0 + cv);
        }
    };

    const int T = K >> 5;
    load_stage(0, 0);  cp_commit();
    load_stage(1, 32); cp_commit();

    int st = 0;   // it % 3
    for (int it = 0; it < T; it++){
        asm volatile("cp.async.wait_group 1;" ::: "memory");
        __syncthreads();
        if (it + 2 < T){
            int sp = st + 2; if (sp >= 3) sp -= 3;
            load_stage(sp, (it+2) << 5);
        }
        cp_commit();
        const __half* sA = smg + st*GSLOT;
        const __half* sB = sA + GBM*GSTR;
        #pragma unroll
        for (int kk = 0; kk < GBK; kk += 16){
            uint32_t af[4][4], bfr[4][2];
            #pragma unroll
            for (int mi=0; mi<4; mi++){
                uint32_t addr = smem_u32(sA + (aRow + mi*16)*GSTR + kk + aColOff);
                ldsm_x4(af[mi][0], af[mi][1], af[mi][2], af[mi][3], addr);
            }
            #pragma unroll
            for (int np=0; np<2; np++){
                uint32_t addr = smem_u32(sB + (bRow + np*16)*GSTR + kk + bColOff);
                ldsm_x4(bfr[2*np][0], bfr[2*np][1], bfr[2*np+1][0], bfr[2*np+1][1], addr);
            }
            #pragma unroll
            for (int mi=0; mi<4; mi++)
                #pragma unroll
                for (int ni=0; ni<4; ni++)
                    mma_h(acc[mi][ni], af[mi][0], af[mi][1], af[mi][2], af[mi][3],
                          bfr[ni][0], bfr[ni][1]);
        }
        if (++st >= 3) st -= 3;
    }

    if (MODE == 4){
        // ---- fused q/k LayerNorm + head transpose epilogue (f16 staging) ----
        __half* sT = smg;                                // 128 x TSTR_H f16
        __half* sStage = smg + 128*TSTR_H;               // 128x32 f16
        __syncthreads();
        #pragma unroll
        for (int mi=0; mi<4; mi++){
            int r0 = wm*64 + mi*16 + gid;
            #pragma unroll
            for (int ni=0; ni<4; ni++){
                int c = wn*32 + ni*8 + tig*2;
                float b0 = bias[bn + c], b1 = bias[bn + c + 1];
                float2 lo = __half22float2(*(__half2*)&acc[mi][ni][0]);
                float2 hi = __half22float2(*(__half2*)&acc[mi][ni][1]);
                *(__half2*)(sT + r0*TSTR_H + c)     = __floats2half2_rn(lo.x+b0, lo.y+b1);
                *(__half2*)(sT + (r0+8)*TSTR_H + c) = __floats2half2_rn(hi.x+b0, hi.y+b1);
            }
        }
        __syncthreads();
        const int b   = bm / SPA;
        const int ij0 = bm % SPA;
        #pragma unroll
        for (int seg = 0; seg < 4; seg++){
            int segidx = (bn >> 5) + seg;
            int t = segidx % 3, h = segidx / 3;
            const float* lw = (t == 0) ? qw : kw;
            const float* lb = (t == 0) ? qb : kb;
            float wv = (t < 2) ? lw[lane] : 0.f;
            float bv = (t < 2) ? lb[lane] : 0.f;
            for (int rr = 0; rr < 16; rr++){
                int row = warp*16 + rr;
                float val = __half2float(sT[row*TSTR_H + seg*32 + lane]);
                if (t < 2){
                    float mu = wsum(val) * (1.f/32.f);
                    float d  = val - mu;
                    float vr = wsum(d*d) * (1.f/32.f);
                    val = d * rsqrtf(vr + 1e-5f) * wv + bv;
                }
                sStage[row*32 + lane] = __float2half(val);
            }
            __syncthreads();
            __half* dst = ((t == 0) ? g_Qb : (t == 1) ? g_Kb : g_Vb)
                          + ((size_t)(b*NHEADS + h)*SPA + ij0)*HDIM;
            #pragma unroll
            for (int i = tid; i < 512; i += 256)
                ((uint4*)dst)[i] = ((const uint4*)sStage)[i];
            __syncthreads();
        }
        return;
    }

    // standard epilogues
    #pragma unroll
    for (int mi=0; mi<4; mi++){
        int r0 = bm + wm*64 + mi*16 + gid;
        #pragma unroll
        for (int ni=0; ni<4; ni++){
            int c = bn + wn*32 + ni*8 + tig*2;
            float2 lo = __half22float2(*(__half2*)&acc[mi][ni][0]);
            float2 hi = __half22float2(*(__half2*)&acc[mi][ni][1]);
            #pragma unroll
            for (int half2i=0; half2i<2; half2i++){
                int r = r0 + half2i*8;
                float v0 = (half2i ? hi.x : lo.x) + bias[c];
                float v1 = (half2i ? hi.y : lo.y) + bias[c+1];
                size_t o = (size_t)r*Nn + c;
                if (MODE == 1){
                    float y0 = v0*gamma[c]   + res[o];
                    float y1 = v1*gamma[c+1] + res[o+1];
                    *(float2*)(Cf + o) = make_float2(y0, y1);
                    __half2 t = __floats2half2_rn(y0, y1);
                    *(__half2*)(Cb + o) = t;
                } else if (MODE == 2){
                    __half2 t = __floats2half2_rn(gelu_t(v0), gelu_t(v1));
                    *(__half2*)(Cb + o) = t;
                } else {
                    __half2 t = __floats2half2_rn(v0, v1);
                    *(__half2*)(Cb + o) = t;
                }
            }
        }
    }
}

// ---------------- T5 relative position bias ----------------
__global__ void k_bias(const float* __restrict__ emb, const int* __restrict__ bcs){
    int idx = blockIdx.x*256 + threadIdx.x;
    int dir = idx / SPA;
    int qk  = idx % SPA;
    int q = qk / LSEQ, kk = qk % LSEQ;
    int bc = bcs[dir];
    int rel = kk - q;
    if (bc == 1){
        const int thr = LSEQ/2;
        if      (rel < -thr) rel = pymod(rel,  thr);
        else if (rel >  thr) rel = pymod(rel, -thr);
    }
    int n = -rel;
    int ret = (n < 0) ? 16 : 0;
    n = (n < 0) ? -n : n;
    int bucket;
    if (n < 8) bucket = ret + n;
    else {
        int vl = 8 + (int)(logf((float)n * 0.125f) / logf(4.0f) * 8.0f);
        if (vl > 15) vl = 15;
        bucket = ret + vl;
    }
    #pragma unroll
    for (int h = 0; h < NHEADS; h++)
        g_bias[(dir*NHEADS + h)*SPA + qk] = emb[bucket*NHEADS + h];
}

// ---------------- tensor-core axial attention (f16 operands, f32 acc) ----------
#define AQSTR 40
#define AVSTR 106
#define ASSTR 100
#define APSTR 104
#define OFF_K  (96*AQSTR)
#define OFF_VT (2*96*AQSTR)
#define OFF_S_BYTES  ((2*96*AQSTR + 32*AVSTR)*2)
#define OFF_P_BYTES  (OFF_S_BYTES + 96*ASSTR*4)
#define ATT_SMEM (OFF_P_BYTES + 96*APSTR*2)

__global__ void __launch_bounds__(256,2) k_attn(){
    extern __shared__ char smraw[];
    __half* sQ  = (__half*)smraw;
    __half* sK  = sQ + OFF_K;
    __half* sVt = sQ + OFF_VT;
    float*  sS  = (float*)(smraw + OFF_S_BYTES);
    __half* sP  = (__half*)(smraw + OFF_P_BYTES);

    const int line = blockIdx.x;
    const int bh   = blockIdx.y;
    const int dir  = blockIdx.z;
    const int head = bh & (NHEADS-1);
    const int bidx = bh >> 4;
    const int tid  = threadIdx.x;
    const int lane = tid & 31, warp = tid >> 5;
    const int gid  = lane >> 2, tig = lane & 3;
    const int wm   = warp >> 2, wn  = warp & 3;
    const size_t base = (size_t)bh * SPA * HDIM;

    for (int u = tid; u < 1536; u += 256){
        int row = u >> 4;
        int dp  = (u & 15) << 1;
        size_t g = base + dp + (size_t)HDIM * (dir == 0 ? (line*LSEQ + row)
                                                        : (row*LSEQ + line));
        *(uint32_t*)(sQ + row*AQSTR + dp) = *(const uint32_t*)(g_Qb + g);
        *(uint32_t*)(sK + row*AQSTR + dp) = *(const uint32_t*)(g_Kb + g);
        uint32_t vv = *(const uint32_t*)(g_Vb + g);
        __half2 v2 = *(__half2*)&vv;
        sVt[dp*AVSTR + row]     = v2.x;
        sVt[(dp+1)*AVSTR + row] = v2.y;
    }
    __syncthreads();

    {
        float acc[3][3][4];
        #pragma unroll
        for (int mi=0;mi<3;mi++)
            #pragma unroll
            for (int ni=0;ni<3;ni++)
                #pragma unroll
                for (int e=0;e<4;e++) acc[mi][ni][e] = 0.f;
        #pragma unroll
        for (int ks=0; ks<2; ks++){
            int kk = ks*16;
            uint32_t af[3][4], bfr[3][2];
            #pragma unroll
            for (int mi=0;mi<3;mi++){
                const __half* p = sQ + (wm*48 + mi*16 + gid)*AQSTR + kk + tig*2;
                af[mi][0] = *(const uint32_t*)p;
                af[mi][1] = *(const uint32_t*)(p + 8*AQSTR);
                af[mi][2] = *(const uint32_t*)(p + 8);
                af[mi][3] = *(const uint32_t*)(p + 8*AQSTR + 8);
            }
            #pragma unroll
            for (int ni=0;ni<3;ni++){
                const __half* p = sK + (wn*24 + ni*8 + gid)*AQSTR + kk + tig*2;
                bfr[ni][0] = *(const uint32_t*)p;
                bfr[ni][1] = *(const uint32_t*)(p + 8);
            }
            #pragma unroll
            for (int mi=0;mi<3;mi++)
                #pragma unroll
                for (int ni=0;ni<3;ni++)
                    mma_f(acc[mi][ni], af[mi][0], af[mi][1], af[mi][2], af[mi][3],
                          bfr[ni][0], bfr[ni][1]);
        }
        const float* bb = g_bias + (size_t)(dir*NHEADS + head)*SPA;
        const float SC = 0.17677669529663687f;
        #pragma unroll
        for (int mi=0;mi<3;mi++){
            int r = wm*48 + mi*16 + gid;
            #pragma unroll
            for (int ni=0;ni<3;ni++){
                int c = wn*24 + ni*8 + tig*2;
                sS[r*ASSTR + c]       = acc[mi][ni][0]*SC + bb[r*LSEQ + c];
                sS[r*ASSTR + c+1]     = acc[mi][ni][1]*SC + bb[r*LSEQ + c+1];
                sS[(r+8)*ASSTR + c]   = acc[mi][ni][2]*SC + bb[(r+8)*LSEQ + c];
                sS[(r+8)*ASSTR + c+1] = acc[mi][ni][3]*SC + bb[(r+8)*LSEQ + c+1];
            }
        }
    }
    __syncthreads();

    for (int r = warp; r < LSEQ; r += 8){
        const float* row = sS + r*ASSTR;
        float v0 = row[lane], v1 = row[lane+32], v2 = row[lane+64];
        float m = fmaxf(v0, fmaxf(v1, v2));
        #pragma unroll
        for (int o = 16; o; o >>= 1) m = fmaxf(m, __shfl_xor_sync(0xffffffffu, m, o));
        float e0 = __expf(v0 - m), e1 = __expf(v1 - m), e2 = __expf(v2 - m);
        float s = e0 + e1 + e2;
        #pragma unroll
        for (int o = 16; o; o >>= 1) s += __shfl_xor_sync(0xffffffffu, s, o);
        float inv = 1.0f / s;
        __half* pr = sP + r*APSTR;
        pr[lane]    = __float2half(e0*inv);
        pr[lane+32] = __float2half(e1*inv);
        pr[lane+64] = __float2half(e2*inv);
    }
    __syncthreads();

    {
        float po[3][4];
        #pragma unroll
        for (int mi=0;mi<3;mi++)
            #pragma unroll
            for (int e=0;e<4;e++) po[mi][e] = 0.f;
        #pragma unroll
        for (int ks=0; ks<6; ks++){
            int kk = ks*16;
            uint32_t b0 = *(const uint32_t*)(sVt + (wn*8 + gid)*AVSTR + kk + tig*2);
            uint32_t b1 = *(const uint32_t*)(sVt + (wn*8 + gid)*AVSTR + kk + 8 + tig*2);
            #pragma unroll
            for (int mi=0;mi<3;mi++){
                const __half* p = sP + (wm*48 + mi*16 + gid)*APSTR + kk + tig*2;
                uint32_t a0 = *(const uint32_t*)p;
                uint32_t a1 = *(const uint32_t*)(p + 8*APSTR);
                uint32_t a2 = *(const uint32_t*)(p + 8);
                uint32_t a3 = *(const uint32_t*)(p + 8*APSTR + 8);
                mma_f(po[mi], a0, a1, a2, a3, b0, b1);
            }
        }
        __half* outp = dir ? g_attB : g_attA;
        int d = wn*8 + tig*2;
        #pragma unroll
        for (int mi=0;mi<3;mi++){
            int r = wm*48 + mi*16 + gid;
            #pragma unroll
            for (int hf=0; hf<2; hf++){
                int q = r + hf*8;
                int token = (dir == 0) ? ((bidx*LSEQ + line)*LSEQ + q)
                                       : ((bidx*LSEQ + q)*LSEQ + line);
                __half2 t = __floats2half2_rn(po[mi][hf*2], po[mi][hf*2+1]);
                *(__half2*)(outp + (size_t)token*CDIM + head*HDIM + d) = t;
            }
        }
    }
}

// ---------------- launch ----------------
extern "C" void kernel_launch(void* const* d_in, const int* in_sizes, int n_in,
                              void* d_out, int out_size){
    const float* x        = (const float*)d_in[0];
    const float* norm1_w  = (const float*)d_in[1];
    const float* in_w     = (const float*)d_in[2];
    const float* in_b     = (const float*)d_in[3];
    const float* qn_w     = (const float*)d_in[4];
    const float* qn_b     = (const float*)d_in[5];
    const float* kn_w     = (const float*)d_in[6];
    const float* kn_b     = (const float*)d_in[7];
    const float* relpos   = (const float*)d_in[8];
    const float* norm2_w  = (const float*)d_in[9];
    const float* out_w    = (const float*)d_in[10];
    const float* out_b    = (const float*)d_in[11];
    const float* gamma_a  = (const float*)d_in[12];
    const float* fc1_w    = (const float*)d_in[13];
    const float* fc1_b    = (const float*)d_in[14];
    const float* fc2_w    = (const float*)d_in[15];
    const float* fc2_b    = (const float*)d_in[16];
    const float* mlpn_w   = (const float*)d_in[17];
    const float* gamma_m  = (const float*)d_in[18];
    const int*   bcs      = (const int*)d_in[19];
    float* out = (float*)d_out;

    void *xn_p, *win_p, *wout_p, *wfc1_p, *wfc2_p, *attA_p, *attB_p,
         *abf_p, *x1_p, *x1h_p, *h_p, *mb_p;
    cudaGetSymbolAddress(&xn_p,   g_xn);
    cudaGetSymbolAddress(&win_p,  g_win);
    cudaGetSymbolAddress(&wout_p, g_wout);
    cudaGetSymbolAddress(&wfc1_p, g_wfc1);
    cudaGetSymbolAddress(&wfc2_p, g_wfc2);
    cudaGetSymbolAddress(&attA_p, g_attA);
    cudaGetSymbolAddress(&attB_p, g_attB);
    cudaGetSymbolAddress(&abf_p,  g_abf);
    cudaGetSymbolAddress(&x1_p,   g_x1);
    cudaGetSymbolAddress(&x1h_p,  g_x1h);
    cudaGetSymbolAddress(&h_p,    g_h);
    cudaGetSymbolAddress(&mb_p,   g_mb);

    cudaFuncSetAttribute(k_attn,    cudaFuncAttributeMaxDynamicSharedMemorySize, ATT_SMEM);
    cudaFuncSetAttribute(k_gemm<1>, cudaFuncAttributeMaxDynamicSharedMemorySize, GEMM_SMEM);
    cudaFuncSetAttribute(k_gemm<2>, cudaFuncAttributeMaxDynamicSharedMemorySize, GEMM_SMEM);
    cudaFuncSetAttribute(k_gemm<3>, cudaFuncAttributeMaxDynamicSharedMemorySize, GEMM_SMEM);
    cudaFuncSetAttribute(k_gemm<4>, cudaFuncAttributeMaxDynamicSharedMemorySize, GEMM_SMEM);

    const int ELW4 = (NTOK*CDIM)/4/256;

    // 1-3: norm1 stats/scale/apply (+ all weight conversions piggybacked)
    k_stats<float><<<dim3(SPA/32, BBATCH), 128>>>(x, nullptr);
    k_scale<<<4,256>>>(norm1_w, nullptr, 1e-8f);
    k_apply<float><<<ELW4,256>>>(x, nullptr, (__half*)xn_p,
        in_w,  (__half*)win_p,  out_w, (__half*)wout_p,
        fc1_w, (__half*)wfc1_p, fc2_w, (__half*)wfc2_p);

    // 4: qkv projection + fused q/k LN + transpose (PROFILED SLOT)
    k_gemm<4><<<dim3(C3/GBN, NTOK/GBM), 256, GEMM_SMEM>>>((const __half*)xn_p,
        (const __half*)win_p, in_b, nullptr, nullptr, nullptr, nullptr,
        qn_w, qn_b, kn_w, kn_b, C3, CDIM);

    // 5: relative position bias
    k_bias<<<(2*SPA)/256, 256>>>(relpos, bcs);

    // 6: axial attention
    k_attn<<<dim3(LSEQ, BBATCH*NHEADS, 2), 256, ATT_SMEM>>>();

    // 7-9: norm2 on 0.5*(xx+xy) -> abf
    k_stats<__half><<<dim3(SPA/32, BBATCH), 128>>>(
        (const __half*)attA_p, (const __half*)attB_p);
    k_scale<<<4,256>>>(norm2_w, nullptr, 1e-8f);
    k_apply<__half><<<ELW4,256>>>((const __half*)attA_p,
        (const __half*)attB_p, (__half*)abf_p,
        nullptr, nullptr, nullptr, nullptr, nullptr, nullptr, nullptr, nullptr);

    // 10: out projection, fused x1 = a*gamma_att + x
    k_gemm<1><<<dim3(CDIM/GBN, NTOK/GBM), 256, GEMM_SMEM>>>((const __half*)abf_p,
        (const __half*)wout_p, out_b, gamma_a, x,
        (float*)x1_p, (__half*)x1h_p,
        nullptr, nullptr, nullptr, nullptr, CDIM, CDIM);

    // 11: fc1 + gelu -> h
    k_gemm<2><<<dim3(CH/GBN, NTOK/GBM), 256, GEMM_SMEM>>>((const __half*)x1h_p,
        (const __half*)wfc1_p, fc1_b, nullptr, nullptr,
        nullptr, (__half*)h_p,
        nullptr, nullptr, nullptr, nullptr, CH, CDIM);

    // 12: fc2 -> m
    k_gemm<3><<<dim3(CDIM/GBN, NTOK/GBM), 256, GEMM_SMEM>>>((const __half*)h_p,
        (const __half*)wfc2_p, fc2_b, nullptr, nullptr,
        nullptr, (__half*)mb_p,
        nullptr, nullptr, nullptr, nullptr, CDIM, CH);

    // 13-15: mlpn norm + final add
    k_stats<__half><<<dim3(SPA/32, BBATCH), 128>>>(
        (const __half*)mb_p, nullptr);
    k_scale<<<4,256>>>(mlpn_w, gamma_m, 1e-8f);
    k_final<<<ELW4,256>>>(out);
}